// round 13
// baseline (speedup 1.0000x reference)
#include <cuda_runtime.h>
#include <math.h>
#include <stdint.h>

#define NN      10000
#define EE      320000
#define EALL    (EE + NN)
#define BGRAPH  64
#define NEDGES_OUT 1024
#define CAP     256

// ---------------- scratch ----------------
__device__ __align__(16) float g_h  [NN * 256];
__device__ __align__(16) float g_h2 [NN * 256];   // split-K partial (z=1)
__device__ __align__(16) float g_o1 [NN * 256];
__device__ __align__(16) float g_o2 [NN * 256];
__device__ __align__(16) float g_o3 [NN * 64];
__device__ __align__(16) float g_s  [NN * 4];
__device__ __align__(16) float g_dt [NN * 4];
__device__ int   g_deg [NN + 1];   // static zero-init; scan resets to 0 each run
__device__ int   g_ptr [NN + 1];
__device__ int   g_rank[EALL];
__device__ int   g_csr [EALL];

// ---------------- f32x2 helpers ----------------
__device__ __forceinline__ void fma2(uint64_t& d, uint64_t a, uint64_t b) {
    asm("fma.rn.f32x2 %0,%1,%2,%0;" : "+l"(d) : "l"(a), "l"(b));
}
__device__ __forceinline__ uint64_t dup2(float v) {
    uint64_t r; asm("mov.b64 %0,{%1,%1};" : "=l"(r) : "f"(v)); return r;
}
__device__ __forceinline__ float2 upk2(uint64_t v) {
    float2 r; asm("mov.b64 {%0,%1},%2;" : "=f"(r.x), "=f"(r.y) : "l"(v)); return r;
}
__device__ __forceinline__ float leaky02(float z) { return z > 0.f ? z : 0.2f * z; }

// ---------------- CSR build ----------------
__global__ void count_deg_kernel(const int* __restrict__ ei) {
    int e = blockIdx.x * blockDim.x + threadIdx.x;
    if (e >= EALL) return;
    int dst = (e < EE) ? ei[EE + e] : (e - EE);
    g_rank[e] = atomicAdd(&g_deg[dst], 1);
}

__global__ void scan_kernel() {
    __shared__ int sh[1024];
    const int t = threadIdx.x;
    const int PER = (NN + 1023) / 1024;
    int start = t * PER;
    int sum = 0;
    for (int i = 0; i < PER; i++) {
        int idx = start + i;
        if (idx < NN) sum += g_deg[idx];
    }
    sh[t] = sum;
    __syncthreads();
    for (int off = 1; off < 1024; off <<= 1) {
        int v = (t >= off) ? sh[t - off] : 0;
        __syncthreads();
        sh[t] += v;
        __syncthreads();
    }
    int run = (t == 0) ? 0 : sh[t - 1];
    for (int i = 0; i < PER; i++) {
        int idx = start + i;
        if (idx < NN) {
            int d = g_deg[idx];
            g_ptr[idx] = run;
            run += d;
            g_deg[idx] = 0;
        }
    }
    if (t == 1023) g_ptr[NN] = sh[1023];
}

__global__ void scatter_kernel(const int* __restrict__ ei) {
    int e = blockIdx.x * blockDim.x + threadIdx.x;
    if (e >= EALL) return;
    int src, dst;
    if (e < EE) { src = ei[e]; dst = ei[EE + e]; }
    else        { src = e - EE; dst = e - EE; }
    g_csr[g_ptr[dst] + g_rank[e]] = src;
}

// ---------------- SGEMM: 64 x TN tile, 128 threads, 8xTC f32x2 microtile ----------
// Optional split-K: gridDim.z halves select k-slice [z*128, z*128+Klen) and output
// buffer (z=0 -> g_h, z=1 -> g_h2). do_epi=1 computes the fused s/d attention dots.
template <int TN, int H>
__global__ __launch_bounds__(128, 4)
void sgemm_fused_kernel(const float* __restrict__ Aext, int asel,
                        const float* __restrict__ W,
                        const float* __restrict__ as_, const float* __restrict__ ad_,
                        int M, int lda, int Klen, int do_epi) {
    constexpr int TC = TN / 16;
    constexpr int NCOL = H * 64;
    constexpr int NB4 = TN / 4;
    constexpr int BSTRIDE = 128 / NB4;
    constexpr int BIT = 16 / BSTRIDE;
    __shared__ float sAT[2][16][64];
    __shared__ float sB [2][16][TN];

    const int t  = threadIdx.x;
    const int tx = t & 15, ty = t >> 4;
    const int brow = blockIdx.y * 64;
    const int bcol = blockIdx.x * TN;
    const int kbase = blockIdx.z * 128;            // split-K slice
    float* __restrict__ Cout = (blockIdx.z == 0) ? g_h : g_h2;

    const int arow = t & 63;
    const int kgA  = (t >> 6) * 8;
    const bool aok = (brow + arow) < M;
    const int bc4 = (t % NB4) * 4;
    const int bkr = t / NB4;

    const float* __restrict__ A = (asel == 0) ? Aext
                                  : (asel == 1 ? (const float*)g_o1 : (const float*)g_o2);

    uint64_t acc[4][TC];
#pragma unroll
    for (int p = 0; p < 4; p++)
#pragma unroll
        for (int j = 0; j < TC; j++) acc[p][j] = 0ull;

    const int KT = Klen >> 4;
    float4 pa0, pa1, pbv[BIT];

    {
        const float* ap = A + (size_t)(brow + arow) * lda + kbase + kgA;
        if (aok) { pa0 = *reinterpret_cast<const float4*>(ap);
                   pa1 = *reinterpret_cast<const float4*>(ap + 4); }
        else     { pa0 = make_float4(0.f,0.f,0.f,0.f); pa1 = pa0; }
#pragma unroll
        for (int i = 0; i < BIT; i++)
            pbv[i] = *reinterpret_cast<const float4*>(
                W + (size_t)(kbase + bkr + i * BSTRIDE) * NCOL + bcol + bc4);
    }
    sAT[0][kgA + 0][arow] = pa0.x; sAT[0][kgA + 1][arow] = pa0.y;
    sAT[0][kgA + 2][arow] = pa0.z; sAT[0][kgA + 3][arow] = pa0.w;
    sAT[0][kgA + 4][arow] = pa1.x; sAT[0][kgA + 5][arow] = pa1.y;
    sAT[0][kgA + 6][arow] = pa1.z; sAT[0][kgA + 7][arow] = pa1.w;
#pragma unroll
    for (int i = 0; i < BIT; i++)
        *reinterpret_cast<float4*>(&sB[0][bkr + i * BSTRIDE][bc4]) = pbv[i];
    __syncthreads();

    for (int kt = 0; kt < KT; kt++) {
        const int p = kt & 1;
        const bool more = (kt + 1) < KT;
        if (more) {
            const int k0 = (kt + 1) * 16;
            const float* ap = A + (size_t)(brow + arow) * lda + kbase + k0 + kgA;
            if (aok) { pa0 = *reinterpret_cast<const float4*>(ap);
                       pa1 = *reinterpret_cast<const float4*>(ap + 4); }
            else     { pa0 = make_float4(0.f,0.f,0.f,0.f); pa1 = pa0; }
#pragma unroll
            for (int i = 0; i < BIT; i++)
                pbv[i] = *reinterpret_cast<const float4*>(
                    W + (size_t)(kbase + k0 + bkr + i * BSTRIDE) * NCOL + bcol + bc4);
        }
#pragma unroll
        for (int kk = 0; kk < 16; kk++) {
            ulonglong2 a01 = *reinterpret_cast<const ulonglong2*>(&sAT[p][kk][ty * 8]);
            ulonglong2 a23 = *reinterpret_cast<const ulonglong2*>(&sAT[p][kk][ty * 8 + 4]);
            float4 B0 = *reinterpret_cast<const float4*>(&sB[p][kk][tx * TC]);
            uint64_t bd[TC];
            bd[0] = dup2(B0.x); bd[1] = dup2(B0.y); bd[2] = dup2(B0.z); bd[3] = dup2(B0.w);
            if (TC == 8) {
                float4 B1 = *reinterpret_cast<const float4*>(&sB[p][kk][tx * TC + 4]);
                bd[4] = dup2(B1.x); bd[5] = dup2(B1.y); bd[6] = dup2(B1.z); bd[7] = dup2(B1.w);
            }
#pragma unroll
            for (int j = 0; j < TC; j++) {
                fma2(acc[0][j], a01.x, bd[j]);
                fma2(acc[1][j], a01.y, bd[j]);
                fma2(acc[2][j], a23.x, bd[j]);
                fma2(acc[3][j], a23.y, bd[j]);
            }
        }
        __syncthreads();
        if (more) {
            const int q = (kt + 1) & 1;
            sAT[q][kgA + 0][arow] = pa0.x; sAT[q][kgA + 1][arow] = pa0.y;
            sAT[q][kgA + 2][arow] = pa0.z; sAT[q][kgA + 3][arow] = pa0.w;
            sAT[q][kgA + 4][arow] = pa1.x; sAT[q][kgA + 5][arow] = pa1.y;
            sAT[q][kgA + 6][arow] = pa1.z; sAT[q][kgA + 7][arow] = pa1.w;
#pragma unroll
            for (int i = 0; i < BIT; i++)
                *reinterpret_cast<float4*>(&sB[q][bkr + i * BSTRIDE][bc4]) = pbv[i];
            __syncthreads();
        }
    }

    float c[8][TC];
#pragma unroll
    for (int rp = 0; rp < 4; rp++)
#pragma unroll
        for (int j = 0; j < TC; j++) {
            float2 u = upk2(acc[rp][j]);
            c[2*rp][j] = u.x; c[2*rp+1][j] = u.y;
        }

    const int col0 = bcol + tx * TC;
    const int head = col0 >> 6;
    constexpr int G = 64 / TC;

    if (do_epi) {
        float avv[TC], dvv[TC];
#pragma unroll
        for (int j = 0; j < TC; j++) {
            avv[j] = as_[head * 64 + ((col0 + j) & 63)];
            dvv[j] = ad_[head * 64 + ((col0 + j) & 63)];
        }
#pragma unroll
        for (int r = 0; r < 8; r++) {
            int rg = brow + ty * 8 + r;
            bool ok = rg < M;
            if (ok) {
                float* cp = Cout + (size_t)rg * NCOL + col0;
#pragma unroll
                for (int j = 0; j < TC; j += 4)
                    *reinterpret_cast<float4*>(cp + j) =
                        make_float4(c[r][j], c[r][j+1], c[r][j+2], c[r][j+3]);
            }
            float sv = 0.f, dv = 0.f;
#pragma unroll
            for (int j = 0; j < TC; j++) { sv += c[r][j] * avv[j]; dv += c[r][j] * dvv[j]; }
#pragma unroll
            for (int o = G / 2; o > 0; o >>= 1) {
                sv += __shfl_xor_sync(0xffffffffu, sv, o);
                dv += __shfl_xor_sync(0xffffffffu, dv, o);
            }
            if (ok && (tx % G) == 0) {
                g_s [rg * 4 + head] = sv;
                g_dt[rg * 4 + head] = dv;
            }
        }
    } else {
#pragma unroll
        for (int r = 0; r < 8; r++) {
            int rg = brow + ty * 8 + r;
            if (rg < M) {
                float* cp = Cout + (size_t)rg * NCOL + col0;
#pragma unroll
                for (int j = 0; j < TC; j += 4)
                    *reinterpret_cast<float4*>(cp + j) =
                        make_float4(c[r][j], c[r][j+1], c[r][j+2], c[r][j+3]);
            }
        }
    }
}

// ---------------- split-K combine + s/d epilogue (one warp per row) ----------------
__global__ void combine_sd_kernel(const float* __restrict__ as_,
                                  const float* __restrict__ ad_) {
    const int warp = threadIdx.x >> 5, lane = threadIdx.x & 31;
    const int r = blockIdx.x * 8 + warp;           // grid 1250 * 8 = 10000
    const int c0 = lane * 8;
    float* __restrict__ hp = g_h + (size_t)r * 256 + c0;
    const float* __restrict__ hq = g_h2 + (size_t)r * 256 + c0;
    float4 a0 = *reinterpret_cast<const float4*>(hp);
    float4 a1 = *reinterpret_cast<const float4*>(hp + 4);
    float4 b0 = *reinterpret_cast<const float4*>(hq);
    float4 b1 = *reinterpret_cast<const float4*>(hq + 4);
    float s_[8];
    s_[0]=a0.x+b0.x; s_[1]=a0.y+b0.y; s_[2]=a0.z+b0.z; s_[3]=a0.w+b0.w;
    s_[4]=a1.x+b1.x; s_[5]=a1.y+b1.y; s_[6]=a1.z+b1.z; s_[7]=a1.w+b1.w;
    *reinterpret_cast<float4*>(hp)     = make_float4(s_[0], s_[1], s_[2], s_[3]);
    *reinterpret_cast<float4*>(hp + 4) = make_float4(s_[4], s_[5], s_[6], s_[7]);
    const int head = lane >> 3;
    const int cih  = (lane & 7) * 8;
    float sv = 0.f, dv = 0.f;
#pragma unroll
    for (int j = 0; j < 8; j++) {
        sv += s_[j] * as_[head * 64 + cih + j];
        dv += s_[j] * ad_[head * 64 + cih + j];
    }
#pragma unroll
    for (int o = 4; o > 0; o >>= 1) {
        sv += __shfl_xor_sync(0xffffffffu, sv, o);
        dv += __shfl_xor_sync(0xffffffffu, dv, o);
    }
    if ((lane & 7) == 0) {
        g_s [r * 4 + head] = sv;
        g_dt[r * 4 + head] = dv;
    }
}

// ---------------- GAT aggregation H=4: 64 threads, float4/thread ----------------
__global__ void gat_agg4_kernel(const float* __restrict__ bias, int osel) {
    float* __restrict__ outp = (osel == 1) ? g_o1 : g_o2;
    const int v = blockIdx.x;
    const int t = threadIdx.x;          // 64
    const int lane = t & 31, warp = t >> 5;
    const int hd = t >> 4;
    const int p0 = g_ptr[v];
    const int deg = g_ptr[v + 1] - p0;

    __shared__ float sh_ws[4];
    __shared__ float sh_m[4];
    __shared__ int   sh_src[CAP];
    __shared__ float sh_w[CAP * 4];

    float dt[4];
    {
        float4 d4 = *reinterpret_cast<const float4*>(&g_dt[v * 4]);
        dt[0] = d4.x; dt[1] = d4.y; dt[2] = d4.z; dt[3] = d4.w;
    }

    if (deg <= CAP) {
        for (int e = t; e < deg; e += 64) {
            int sN = g_csr[p0 + e];
            sh_src[e] = sN;
            float4 s4 = *reinterpret_cast<const float4*>(&g_s[sN * 4]);
            sh_w[e * 4 + 0] = leaky02(s4.x + dt[0]);
            sh_w[e * 4 + 1] = leaky02(s4.y + dt[1]);
            sh_w[e * 4 + 2] = leaky02(s4.z + dt[2]);
            sh_w[e * 4 + 3] = leaky02(s4.w + dt[3]);
        }
        __syncthreads();
#pragma unroll
        for (int k = 0; k < 2; k++) {
            int hh = warp * 2 + k;
            float mx = -1e30f;
            for (int e = lane; e < deg; e += 32) mx = fmaxf(mx, sh_w[e * 4 + hh]);
#pragma unroll
            for (int o = 16; o > 0; o >>= 1) mx = fmaxf(mx, __shfl_xor_sync(0xffffffffu, mx, o));
            float sum = 0.f;
            for (int e = lane; e < deg; e += 32) {
                float w_ = __expf(sh_w[e * 4 + hh] - mx);
                sh_w[e * 4 + hh] = w_;
                sum += w_;
            }
#pragma unroll
            for (int o = 16; o > 0; o >>= 1) sum += __shfl_xor_sync(0xffffffffu, sum, o);
            if (lane == 0) sh_ws[hh] = sum;
        }
        __syncthreads();

        float4 acc = make_float4(0.f, 0.f, 0.f, 0.f);
        const float* __restrict__ hb = g_h + t * 4;
        int e = 0;
        for (; e + 3 < deg; e += 4) {
            float w0 = sh_w[(e+0)*4 + hd], w1 = sh_w[(e+1)*4 + hd];
            float w2 = sh_w[(e+2)*4 + hd], w3 = sh_w[(e+3)*4 + hd];
            float4 h0 = *reinterpret_cast<const float4*>(hb + (size_t)sh_src[e+0] * 256);
            float4 h1 = *reinterpret_cast<const float4*>(hb + (size_t)sh_src[e+1] * 256);
            float4 h2 = *reinterpret_cast<const float4*>(hb + (size_t)sh_src[e+2] * 256);
            float4 h3 = *reinterpret_cast<const float4*>(hb + (size_t)sh_src[e+3] * 256);
            acc.x += w0*h0.x + w1*h1.x + w2*h2.x + w3*h3.x;
            acc.y += w0*h0.y + w1*h1.y + w2*h2.y + w3*h3.y;
            acc.z += w0*h0.z + w1*h1.z + w2*h2.z + w3*h3.z;
            acc.w += w0*h0.w + w1*h1.w + w2*h2.w + w3*h3.w;
        }
        for (; e < deg; e++) {
            float w_ = sh_w[e*4 + hd];
            float4 h_ = *reinterpret_cast<const float4*>(hb + (size_t)sh_src[e] * 256);
            acc.x += w_*h_.x; acc.y += w_*h_.y; acc.z += w_*h_.z; acc.w += w_*h_.w;
        }
        float inv = 1.f / sh_ws[hd];
        float4 b4 = *reinterpret_cast<const float4*>(&bias[t * 4]);
        float4 o;
        o.x = fmaxf(acc.x * inv + b4.x, 0.f);
        o.y = fmaxf(acc.y * inv + b4.y, 0.f);
        o.z = fmaxf(acc.z * inv + b4.z, 0.f);
        o.w = fmaxf(acc.w * inv + b4.w, 0.f);
        *reinterpret_cast<float4*>(&outp[(size_t)v * 256 + t * 4]) = o;
        return;
    }

    // ---- fallback deg > CAP ----
#pragma unroll
    for (int k = 0; k < 2; k++) {
        int hh = warp * 2 + k;
        float mx = -1e30f;
        for (int e = lane; e < deg; e += 32) {
            int sN = g_csr[p0 + e];
            mx = fmaxf(mx, leaky02(g_s[sN * 4 + hh] + dt[hh]));
        }
#pragma unroll
        for (int o = 16; o > 0; o >>= 1) mx = fmaxf(mx, __shfl_xor_sync(0xffffffffu, mx, o));
        float sum = 0.f;
        for (int e = lane; e < deg; e += 32) {
            int sN = g_csr[p0 + e];
            sum += __expf(leaky02(g_s[sN * 4 + hh] + dt[hh]) - mx);
        }
#pragma unroll
        for (int o = 16; o > 0; o >>= 1) sum += __shfl_xor_sync(0xffffffffu, sum, o);
        if (lane == 0) { sh_m[hh] = mx; sh_ws[hh] = sum; }
    }
    __syncthreads();

    float4 acc = make_float4(0.f, 0.f, 0.f, 0.f);
    const float* __restrict__ hb = g_h + t * 4;
    for (int base = 0; base < deg; base += CAP) {
        int cnt = min(CAP, deg - base);
        for (int e = t; e < cnt; e += 64) {
            int sN = g_csr[p0 + base + e];
            sh_src[e] = sN;
            float4 s4 = *reinterpret_cast<const float4*>(&g_s[sN * 4]);
            sh_w[e*4+0] = __expf(leaky02(s4.x + dt[0]) - sh_m[0]);
            sh_w[e*4+1] = __expf(leaky02(s4.y + dt[1]) - sh_m[1]);
            sh_w[e*4+2] = __expf(leaky02(s4.z + dt[2]) - sh_m[2]);
            sh_w[e*4+3] = __expf(leaky02(s4.w + dt[3]) - sh_m[3]);
        }
        __syncthreads();
        for (int e = 0; e < cnt; e++) {
            float w_ = sh_w[e*4 + hd];
            float4 h_ = *reinterpret_cast<const float4*>(hb + (size_t)sh_src[e] * 256);
            acc.x += w_*h_.x; acc.y += w_*h_.y; acc.z += w_*h_.z; acc.w += w_*h_.w;
        }
        __syncthreads();
    }
    float inv = 1.f / sh_ws[hd];
    float4 b4 = *reinterpret_cast<const float4*>(&bias[t * 4]);
    float4 o;
    o.x = fmaxf(acc.x * inv + b4.x, 0.f);
    o.y = fmaxf(acc.y * inv + b4.y, 0.f);
    o.z = fmaxf(acc.z * inv + b4.z, 0.f);
    o.w = fmaxf(acc.w * inv + b4.w, 0.f);
    *reinterpret_cast<float4*>(&outp[(size_t)v * 256 + t * 4]) = o;
}

// ---------------- GAT aggregation H=1 (layer 3) ----------------
__global__ void gat_agg1_kernel(const float* __restrict__ bias) {
    float* __restrict__ outp = g_o3;
    const int v = blockIdx.x;
    const int t = threadIdx.x;      // 64
    const int lane = t & 31, warp = t >> 5;
    const int p0 = g_ptr[v];
    const int deg = g_ptr[v + 1] - p0;

    __shared__ float sh_ws[1];
    __shared__ float sh_m[1];
    __shared__ int   sh_src[CAP];
    __shared__ float sh_w[CAP];

    float dt0 = g_dt[v * 4];

    if (deg <= CAP) {
        for (int e = t; e < deg; e += 64) {
            int sN = g_csr[p0 + e];
            sh_src[e] = sN;
            sh_w[e] = leaky02(g_s[sN * 4] + dt0);
        }
        __syncthreads();
        if (warp == 0) {
            float mx = -1e30f;
            for (int e = lane; e < deg; e += 32) mx = fmaxf(mx, sh_w[e]);
#pragma unroll
            for (int o = 16; o > 0; o >>= 1) mx = fmaxf(mx, __shfl_xor_sync(0xffffffffu, mx, o));
            float sum = 0.f;
            for (int e = lane; e < deg; e += 32) {
                float w_ = __expf(sh_w[e] - mx);
                sh_w[e] = w_;
                sum += w_;
            }
#pragma unroll
            for (int o = 16; o > 0; o >>= 1) sum += __shfl_xor_sync(0xffffffffu, sum, o);
            if (lane == 0) sh_ws[0] = sum;
        }
        __syncthreads();

        float acc = 0.f;
        int e = 0;
        for (; e + 3 < deg; e += 4) {
            acc += sh_w[e+0] * g_h[(size_t)sh_src[e+0] * 64 + t];
            acc += sh_w[e+1] * g_h[(size_t)sh_src[e+1] * 64 + t];
            acc += sh_w[e+2] * g_h[(size_t)sh_src[e+2] * 64 + t];
            acc += sh_w[e+3] * g_h[(size_t)sh_src[e+3] * 64 + t];
        }
        for (; e < deg; e++) acc += sh_w[e] * g_h[(size_t)sh_src[e] * 64 + t];
        float o = acc / sh_ws[0] + bias[t];
        outp[(size_t)v * 64 + t] = fmaxf(o, 0.f);
        return;
    }

    if (warp == 0) {
        float mx = -1e30f;
        for (int e = lane; e < deg; e += 32) {
            int sN = g_csr[p0 + e];
            mx = fmaxf(mx, leaky02(g_s[sN * 4] + dt0));
        }
#pragma unroll
        for (int o = 16; o > 0; o >>= 1) mx = fmaxf(mx, __shfl_xor_sync(0xffffffffu, mx, o));
        float sum = 0.f;
        for (int e = lane; e < deg; e += 32) {
            int sN = g_csr[p0 + e];
            sum += __expf(leaky02(g_s[sN * 4] + dt0) - mx);
        }
#pragma unroll
        for (int o = 16; o > 0; o >>= 1) sum += __shfl_xor_sync(0xffffffffu, sum, o);
        if (lane == 0) { sh_m[0] = mx; sh_ws[0] = sum; }
    }
    __syncthreads();

    float acc = 0.f;
    for (int base = 0; base < deg; base += CAP) {
        int cnt = min(CAP, deg - base);
        for (int e = t; e < cnt; e += 64) {
            int sN = g_csr[p0 + base + e];
            sh_src[e] = sN;
            sh_w[e] = __expf(leaky02(g_s[sN * 4] + dt0) - sh_m[0]);
        }
        __syncthreads();
        for (int e = 0; e < cnt; e++)
            acc += sh_w[e] * g_h[(size_t)sh_src[e] * 64 + t];
        __syncthreads();
    }
    float o = acc / sh_ws[0] + bias[t];
    outp[(size_t)v * 64 + t] = fmaxf(o, 0.f);
}

// ---------------- fused pool + actor/critic heads ----------------
__global__ void heads_pool_kernel(const int* __restrict__ batch,
                                  const float* __restrict__ Wa1, const float* __restrict__ ba1,
                                  const float* __restrict__ Wa2, const float* __restrict__ ba2,
                                  const float* __restrict__ Wc1, const float* __restrict__ bc1,
                                  const float* __restrict__ Wc2, const float* __restrict__ bc2,
                                  float* __restrict__ out) {
    const int b = blockIdx.x;
    const int t = threadIdx.x;
    int lo = 0, hi = NN;
    while (lo < hi) { int mid = (lo + hi) >> 1; if (batch[mid] < b) lo = mid + 1; else hi = mid; }
    int start = lo;
    lo = start; hi = NN;
    while (lo < hi) { int mid = (lo + hi) >> 1; if (batch[mid] < b + 1) lo = mid + 1; else hi = mid; }
    int end = lo;
    int cnt = end - start;

    __shared__ float red[256];
    __shared__ float p[64], ha[64], hc[64];
    const int c = t & 63, stripe = t >> 6;
    float part = 0.f;
    for (int n = start + stripe; n < end; n += 4) part += g_o3[n * 64 + c];
    red[t] = part;
    __syncthreads();
    if (t < 64) {
        float s = red[t] + red[t + 64] + red[t + 128] + red[t + 192];
        float cc = cnt > 0 ? (float)cnt : 1.f;
        p[t] = s / cc;
    }
    __syncthreads();
    if (t < 64) {
        float aa = ba1[t], cv = bc1[t];
        for (int j = 0; j < 64; j++) { aa += p[j] * Wa1[j * 64 + t]; cv += p[j] * Wc1[j * 64 + t]; }
        ha[t] = fmaxf(aa, 0.f);
        hc[t] = fmaxf(cv, 0.f);
    }
    __syncthreads();
    for (int o = t; o < NEDGES_OUT; o += blockDim.x) {
        float acc = ba2[o];
        for (int j = 0; j < 64; j++) acc += ha[j] * Wa2[j * NEDGES_OUT + o];
        out[b * NEDGES_OUT + o] = tanhf(acc);
    }
    if (t == 0) {
        float acc = bc2[0];
        for (int j = 0; j < 64; j++) acc += hc[j] * Wc2[j];
        out[BGRAPH * NEDGES_OUT + b] = acc;
    }
}

// ---------------- launch ----------------
extern "C" void kernel_launch(void* const* d_in, const int* in_sizes, int n_in,
                              void* d_out, int out_size) {
    const float* x     = (const float*)d_in[0];
    const int*   ei    = (const int*)d_in[1];
    const int*   batch = (const int*)d_in[2];
    const float* W1  = (const float*)d_in[3];
    const float* as1 = (const float*)d_in[4];
    const float* ad1 = (const float*)d_in[5];
    const float* b1  = (const float*)d_in[6];
    const float* W2  = (const float*)d_in[7];
    const float* as2 = (const float*)d_in[8];
    const float* ad2 = (const float*)d_in[9];
    const float* b2  = (const float*)d_in[10];
    const float* W3  = (const float*)d_in[11];
    const float* as3 = (const float*)d_in[12];
    const float* ad3 = (const float*)d_in[13];
    const float* b3  = (const float*)d_in[14];
    const float* Wa1 = (const float*)d_in[15];
    const float* ba1 = (const float*)d_in[16];
    const float* Wa2 = (const float*)d_in[17];
    const float* ba2 = (const float*)d_in[18];
    const float* Wc1 = (const float*)d_in[19];
    const float* bc1 = (const float*)d_in[20];
    const float* Wc2 = (const float*)d_in[21];
    const float* bc2 = (const float*)d_in[22];
    float* out = (float*)d_out;

    static cudaStream_t s_csr = nullptr;
    static cudaEvent_t  ev_fork = nullptr, ev_join = nullptr;
    if (s_csr == nullptr) {
        cudaStreamCreateWithFlags(&s_csr, cudaStreamNonBlocking);
        cudaEventCreateWithFlags(&ev_fork, cudaEventDisableTiming);
        cudaEventCreateWithFlags(&ev_join, cudaEventDisableTiming);
    }

    const int MB = (NN + 63) / 64;   // 157

    // fork: CSR build concurrent with GEMM1
    cudaEventRecord(ev_fork, 0);
    cudaStreamWaitEvent(s_csr, ev_fork, 0);
    count_deg_kernel<<<(EALL + 255) / 256, 256, 0, s_csr>>>(ei);
    scan_kernel<<<1, 1024, 0, s_csr>>>();
    scatter_kernel<<<(EALL + 255) / 256, 256, 0, s_csr>>>(ei);
    cudaEventRecord(ev_join, s_csr);

    // GEMM1: K=128, lda=128, epilogue on
    sgemm_fused_kernel<128, 4><<<dim3(2, MB, 1), 128>>>(x, 0, W1, as1, ad1, NN, 128, 128, 1);

    cudaStreamWaitEvent(0, ev_join, 0);
    gat_agg4_kernel<<<NN, 64>>>(b1, 1);

    // GEMM2: split-K, z in {0,1} -> k-slices [0,128) and [128,256), partials in g_h/g_h2
    sgemm_fused_kernel<128, 4><<<dim3(2, MB, 2), 128>>>(x, 1, W2, as2, ad2, NN, 256, 128, 0);
    combine_sd_kernel<<<NN / 8, 256>>>(as2, ad2);
    gat_agg4_kernel<<<NN, 64>>>(b2, 2);

    // GEMM3: K=256, lda=256, epilogue on
    sgemm_fused_kernel<64, 1><<<dim3(1, MB, 1), 128>>>(x, 2, W3, as3, ad3, NN, 256, 256, 1);
    gat_agg1_kernel<<<NN, 64>>>(b3);

    heads_pool_kernel<<<BGRAPH, 256>>>(batch, Wa1, ba1, Wa2, ba2, Wc1, bc1, Wc2, bc2, out);
}

// round 14
// speedup vs baseline: 1.0456x; 1.0456x over previous
#include <cuda_runtime.h>
#include <math.h>
#include <stdint.h>

#define NN      10000
#define EE      320000
#define EALL    (EE + NN)
#define BGRAPH  64
#define NEDGES_OUT 1024
#define CAP     256

// ---------------- scratch ----------------
__device__ __align__(16) float g_h  [NN * 256];
__device__ __align__(16) float g_o1 [NN * 256];
__device__ __align__(16) float g_o2 [NN * 256];
__device__ __align__(16) float g_o3 [NN * 64];
__device__ __align__(16) float g_s  [NN * 4];
__device__ __align__(16) float g_dt [NN * 4];
__device__ int   g_deg [NN + 1];   // static zero-init; scan resets to 0 each run
__device__ int   g_ptr [NN + 1];
__device__ int   g_rank[EALL];
__device__ int   g_csr [EALL];

// ---------------- helpers ----------------
__device__ __forceinline__ void fma2(uint64_t& d, uint64_t a, uint64_t b) {
    asm("fma.rn.f32x2 %0,%1,%2,%0;" : "+l"(d) : "l"(a), "l"(b));
}
__device__ __forceinline__ uint64_t dup2(float v) {
    uint64_t r; asm("mov.b64 %0,{%1,%1};" : "=l"(r) : "f"(v)); return r;
}
__device__ __forceinline__ float2 upk2(uint64_t v) {
    float2 r; asm("mov.b64 {%0,%1},%2;" : "=f"(r.x), "=f"(r.y) : "l"(v)); return r;
}
__device__ __forceinline__ float leaky02(float z) { return z > 0.f ? z : 0.2f * z; }
__device__ __forceinline__ void cpa16(void* smem_ptr, const void* gptr) {
    uint32_t sa = (uint32_t)__cvta_generic_to_shared(smem_ptr);
    asm volatile("cp.async.cg.shared.global [%0], [%1], 16;" :: "r"(sa), "l"(gptr));
}

// ---------------- CSR build ----------------
__global__ void count_deg_kernel(const int* __restrict__ ei) {
    int e = blockIdx.x * blockDim.x + threadIdx.x;
    if (e >= EALL) return;
    int dst = (e < EE) ? ei[EE + e] : (e - EE);
    g_rank[e] = atomicAdd(&g_deg[dst], 1);
}

__global__ void scan_kernel() {
    __shared__ int sh[1024];
    const int t = threadIdx.x;
    const int PER = (NN + 1023) / 1024;
    int start = t * PER;
    int sum = 0;
    for (int i = 0; i < PER; i++) {
        int idx = start + i;
        if (idx < NN) sum += g_deg[idx];
    }
    sh[t] = sum;
    __syncthreads();
    for (int off = 1; off < 1024; off <<= 1) {
        int v = (t >= off) ? sh[t - off] : 0;
        __syncthreads();
        sh[t] += v;
        __syncthreads();
    }
    int run = (t == 0) ? 0 : sh[t - 1];
    for (int i = 0; i < PER; i++) {
        int idx = start + i;
        if (idx < NN) {
            int d = g_deg[idx];
            g_ptr[idx] = run;
            run += d;
            g_deg[idx] = 0;
        }
    }
    if (t == 1023) g_ptr[NN] = sh[1023];
}

__global__ void scatter_kernel(const int* __restrict__ ei) {
    int e = blockIdx.x * blockDim.x + threadIdx.x;
    if (e >= EALL) return;
    int src, dst;
    if (e < EE) { src = ei[e]; dst = ei[EE + e]; }
    else        { src = e - EE; dst = e - EE; }
    g_csr[g_ptr[dst] + g_rank[e]] = src;
}

// ---------------- SGEMM: 64 x TN tile, 128 threads, 8xTC f32x2 microtile ----------
// A: register-prefetched, transposed smem (LDS.128 row-pairs).
// B: cp.async double-buffered, issued one full tile ahead.
template <int TN, int H>
__global__ __launch_bounds__(128, 4)
void sgemm_fused_kernel(const float* __restrict__ Aext, int asel,
                        const float* __restrict__ W,
                        const float* __restrict__ as_, const float* __restrict__ ad_,
                        int M, int K) {
    constexpr int TC = TN / 16;
    constexpr int NCOL = H * 64;
    constexpr int NB4 = TN / 4;            // float4's per B k-row
    constexpr int BSTRIDE = 128 / NB4;     // k-rows per loader pass
    constexpr int BIT = 16 / BSTRIDE;      // cp.async per thread per tile
    __shared__ float sAT[2][16][64];
    __shared__ float sB [2][16][TN];

    const int t  = threadIdx.x;            // 128
    const int tx = t & 15, ty = t >> 4;    // ty 0..7
    const int brow = blockIdx.y * 64;
    const int bcol = blockIdx.x * TN;

    const int arow  = t & 63;
    const int kgA   = (t >> 6) * 8;        // 0 or 8
    const int arow_g = min(brow + arow, M - 1);   // clamped (garbage rows guarded at store)
    const int bc4 = (t % NB4) * 4;
    const int bkr = t / NB4;

    const float* __restrict__ A = (asel == 0) ? Aext
                                  : (asel == 1 ? (const float*)g_o1 : (const float*)g_o2);

    uint64_t acc[4][TC];
#pragma unroll
    for (int p = 0; p < 4; p++)
#pragma unroll
        for (int j = 0; j < TC; j++) acc[p][j] = 0ull;

    const int KT = K >> 4;
    float4 pa0, pa1;

    // prologue: A tile0 -> smem, B tile0+tile1 -> cp.async, A tile1 -> regs
    {
        const float* ap = A + (size_t)arow_g * K + kgA;
        pa0 = *reinterpret_cast<const float4*>(ap);
        pa1 = *reinterpret_cast<const float4*>(ap + 4);
        sAT[0][kgA + 0][arow] = pa0.x; sAT[0][kgA + 1][arow] = pa0.y;
        sAT[0][kgA + 2][arow] = pa0.z; sAT[0][kgA + 3][arow] = pa0.w;
        sAT[0][kgA + 4][arow] = pa1.x; sAT[0][kgA + 5][arow] = pa1.y;
        sAT[0][kgA + 6][arow] = pa1.z; sAT[0][kgA + 7][arow] = pa1.w;
#pragma unroll
        for (int i = 0; i < BIT; i++)
            cpa16(&sB[0][bkr + i * BSTRIDE][bc4],
                  W + (size_t)(bkr + i * BSTRIDE) * NCOL + bcol + bc4);
        asm volatile("cp.async.commit_group;");
#pragma unroll
        for (int i = 0; i < BIT; i++)
            cpa16(&sB[1][bkr + i * BSTRIDE][bc4],
                  W + (size_t)(16 + bkr + i * BSTRIDE) * NCOL + bcol + bc4);
        asm volatile("cp.async.commit_group;");
        if (KT > 1) {
            ap = A + (size_t)arow_g * K + 16 + kgA;
            pa0 = *reinterpret_cast<const float4*>(ap);
            pa1 = *reinterpret_cast<const float4*>(ap + 4);
        }
        asm volatile("cp.async.wait_group 1;" ::: "memory");
        __syncthreads();
    }

    for (int kt = 0; kt < KT; kt++) {
        const int p = kt & 1, q = p ^ 1;
#pragma unroll
        for (int kk = 0; kk < 16; kk++) {
            ulonglong2 a01 = *reinterpret_cast<const ulonglong2*>(&sAT[p][kk][ty * 8]);
            ulonglong2 a23 = *reinterpret_cast<const ulonglong2*>(&sAT[p][kk][ty * 8 + 4]);
            float4 B0 = *reinterpret_cast<const float4*>(&sB[p][kk][tx * TC]);
            uint64_t bd[TC];
            bd[0] = dup2(B0.x); bd[1] = dup2(B0.y); bd[2] = dup2(B0.z); bd[3] = dup2(B0.w);
            if (TC == 8) {
                float4 B1 = *reinterpret_cast<const float4*>(&sB[p][kk][tx * TC + 4]);
                bd[4] = dup2(B1.x); bd[5] = dup2(B1.y); bd[6] = dup2(B1.z); bd[7] = dup2(B1.w);
            }
#pragma unroll
            for (int j = 0; j < TC; j++) {
                fma2(acc[0][j], a01.x, bd[j]);
                fma2(acc[1][j], a01.y, bd[j]);
                fma2(acc[2][j], a23.x, bd[j]);
                fma2(acc[3][j], a23.y, bd[j]);
            }
        }
        __syncthreads();     // all warps done reading buffer p (A and B)
        if (kt + 1 < KT) {
            // A(kt+1) regs -> sAT[q]
            sAT[q][kgA + 0][arow] = pa0.x; sAT[q][kgA + 1][arow] = pa0.y;
            sAT[q][kgA + 2][arow] = pa0.z; sAT[q][kgA + 3][arow] = pa0.w;
            sAT[q][kgA + 4][arow] = pa1.x; sAT[q][kgA + 5][arow] = pa1.y;
            sAT[q][kgA + 6][arow] = pa1.z; sAT[q][kgA + 7][arow] = pa1.w;
            if (kt + 2 < KT) {
                const int k0 = (kt + 2) * 16;
                const float* ap = A + (size_t)arow_g * K + k0 + kgA;
                pa0 = *reinterpret_cast<const float4*>(ap);
                pa1 = *reinterpret_cast<const float4*>(ap + 4);
#pragma unroll
                for (int i = 0; i < BIT; i++)
                    cpa16(&sB[p][bkr + i * BSTRIDE][bc4],
                          W + (size_t)(k0 + bkr + i * BSTRIDE) * NCOL + bcol + bc4);
                asm volatile("cp.async.commit_group;");
                asm volatile("cp.async.wait_group 1;" ::: "memory");
            } else {
                asm volatile("cp.async.wait_group 0;" ::: "memory");
            }
            __syncthreads();
        }
    }

    // unpack
    float c[8][TC];
#pragma unroll
    for (int rp = 0; rp < 4; rp++)
#pragma unroll
        for (int j = 0; j < TC; j++) {
            float2 u = upk2(acc[rp][j]);
            c[2*rp][j] = u.x; c[2*rp+1][j] = u.y;
        }

    const int col0 = bcol + tx * TC;
    const int head = col0 >> 6;
    float avv[TC], dvv[TC];
#pragma unroll
    for (int j = 0; j < TC; j++) {
        avv[j] = as_[head * 64 + ((col0 + j) & 63)];
        dvv[j] = ad_[head * 64 + ((col0 + j) & 63)];
    }
    constexpr int G = 64 / TC;

#pragma unroll
    for (int r = 0; r < 8; r++) {
        int rg = brow + ty * 8 + r;
        bool ok = rg < M;
        if (ok) {
            float* cp = g_h + (size_t)rg * NCOL + col0;
#pragma unroll
            for (int j = 0; j < TC; j += 4)
                *reinterpret_cast<float4*>(cp + j) =
                    make_float4(c[r][j], c[r][j+1], c[r][j+2], c[r][j+3]);
        }
        float sv = 0.f, dv = 0.f;
#pragma unroll
        for (int j = 0; j < TC; j++) { sv += c[r][j] * avv[j]; dv += c[r][j] * dvv[j]; }
#pragma unroll
        for (int o = G / 2; o > 0; o >>= 1) {
            sv += __shfl_xor_sync(0xffffffffu, sv, o);
            dv += __shfl_xor_sync(0xffffffffu, dv, o);
        }
        if (ok && (tx % G) == 0) {
            g_s [rg * 4 + head] = sv;
            g_dt[rg * 4 + head] = dv;
        }
    }
}

// ---------------- GAT aggregation H=4: 64 threads, float4/thread ----------------
__global__ void gat_agg4_kernel(const float* __restrict__ bias, int osel) {
    float* __restrict__ outp = (osel == 1) ? g_o1 : g_o2;
    const int v = blockIdx.x;
    const int t = threadIdx.x;          // 64
    const int lane = t & 31, warp = t >> 5;
    const int hd = t >> 4;
    const int p0 = g_ptr[v];
    const int deg = g_ptr[v + 1] - p0;

    __shared__ float sh_ws[4];
    __shared__ float sh_m[4];
    __shared__ int   sh_src[CAP];
    __shared__ float sh_w[CAP * 4];

    float dt[4];
    {
        float4 d4 = *reinterpret_cast<const float4*>(&g_dt[v * 4]);
        dt[0] = d4.x; dt[1] = d4.y; dt[2] = d4.z; dt[3] = d4.w;
    }

    if (deg <= CAP) {
        for (int e = t; e < deg; e += 64) {
            int sN = g_csr[p0 + e];
            sh_src[e] = sN;
            float4 s4 = *reinterpret_cast<const float4*>(&g_s[sN * 4]);
            sh_w[e * 4 + 0] = leaky02(s4.x + dt[0]);
            sh_w[e * 4 + 1] = leaky02(s4.y + dt[1]);
            sh_w[e * 4 + 2] = leaky02(s4.z + dt[2]);
            sh_w[e * 4 + 3] = leaky02(s4.w + dt[3]);
        }
        __syncthreads();
#pragma unroll
        for (int k = 0; k < 2; k++) {
            int hh = warp * 2 + k;
            float mx = -1e30f;
            for (int e = lane; e < deg; e += 32) mx = fmaxf(mx, sh_w[e * 4 + hh]);
#pragma unroll
            for (int o = 16; o > 0; o >>= 1) mx = fmaxf(mx, __shfl_xor_sync(0xffffffffu, mx, o));
            float sum = 0.f;
            for (int e = lane; e < deg; e += 32) {
                float w_ = __expf(sh_w[e * 4 + hh] - mx);
                sh_w[e * 4 + hh] = w_;
                sum += w_;
            }
#pragma unroll
            for (int o = 16; o > 0; o >>= 1) sum += __shfl_xor_sync(0xffffffffu, sum, o);
            if (lane == 0) sh_ws[hh] = sum;
        }
        __syncthreads();

        float4 acc = make_float4(0.f, 0.f, 0.f, 0.f);
        const float* __restrict__ hb = g_h + t * 4;
        int e = 0;
        for (; e + 3 < deg; e += 4) {
            float w0 = sh_w[(e+0)*4 + hd], w1 = sh_w[(e+1)*4 + hd];
            float w2 = sh_w[(e+2)*4 + hd], w3 = sh_w[(e+3)*4 + hd];
            float4 h0 = *reinterpret_cast<const float4*>(hb + (size_t)sh_src[e+0] * 256);
            float4 h1 = *reinterpret_cast<const float4*>(hb + (size_t)sh_src[e+1] * 256);
            float4 h2 = *reinterpret_cast<const float4*>(hb + (size_t)sh_src[e+2] * 256);
            float4 h3 = *reinterpret_cast<const float4*>(hb + (size_t)sh_src[e+3] * 256);
            acc.x += w0*h0.x + w1*h1.x + w2*h2.x + w3*h3.x;
            acc.y += w0*h0.y + w1*h1.y + w2*h2.y + w3*h3.y;
            acc.z += w0*h0.z + w1*h1.z + w2*h2.z + w3*h3.z;
            acc.w += w0*h0.w + w1*h1.w + w2*h2.w + w3*h3.w;
        }
        for (; e < deg; e++) {
            float w_ = sh_w[e*4 + hd];
            float4 h_ = *reinterpret_cast<const float4*>(hb + (size_t)sh_src[e] * 256);
            acc.x += w_*h_.x; acc.y += w_*h_.y; acc.z += w_*h_.z; acc.w += w_*h_.w;
        }
        float inv = 1.f / sh_ws[hd];
        float4 b4 = *reinterpret_cast<const float4*>(&bias[t * 4]);
        float4 o;
        o.x = fmaxf(acc.x * inv + b4.x, 0.f);
        o.y = fmaxf(acc.y * inv + b4.y, 0.f);
        o.z = fmaxf(acc.z * inv + b4.z, 0.f);
        o.w = fmaxf(acc.w * inv + b4.w, 0.f);
        *reinterpret_cast<float4*>(&outp[(size_t)v * 256 + t * 4]) = o;
        return;
    }

    // ---- fallback deg > CAP ----
#pragma unroll
    for (int k = 0; k < 2; k++) {
        int hh = warp * 2 + k;
        float mx = -1e30f;
        for (int e = lane; e < deg; e += 32) {
            int sN = g_csr[p0 + e];
            mx = fmaxf(mx, leaky02(g_s[sN * 4 + hh] + dt[hh]));
        }
#pragma unroll
        for (int o = 16; o > 0; o >>= 1) mx = fmaxf(mx, __shfl_xor_sync(0xffffffffu, mx, o));
        float sum = 0.f;
        for (int e = lane; e < deg; e += 32) {
            int sN = g_csr[p0 + e];
            sum += __expf(leaky02(g_s[sN * 4 + hh] + dt[hh]) - mx);
        }
#pragma unroll
        for (int o = 16; o > 0; o >>= 1) sum += __shfl_xor_sync(0xffffffffu, sum, o);
        if (lane == 0) { sh_m[hh] = mx; sh_ws[hh] = sum; }
    }
    __syncthreads();

    float4 acc = make_float4(0.f, 0.f, 0.f, 0.f);
    const float* __restrict__ hb = g_h + t * 4;
    for (int base = 0; base < deg; base += CAP) {
        int cnt = min(CAP, deg - base);
        for (int e = t; e < cnt; e += 64) {
            int sN = g_csr[p0 + base + e];
            sh_src[e] = sN;
            float4 s4 = *reinterpret_cast<const float4*>(&g_s[sN * 4]);
            sh_w[e*4+0] = __expf(leaky02(s4.x + dt[0]) - sh_m[0]);
            sh_w[e*4+1] = __expf(leaky02(s4.y + dt[1]) - sh_m[1]);
            sh_w[e*4+2] = __expf(leaky02(s4.z + dt[2]) - sh_m[2]);
            sh_w[e*4+3] = __expf(leaky02(s4.w + dt[3]) - sh_m[3]);
        }
        __syncthreads();
        for (int e = 0; e < cnt; e++) {
            float w_ = sh_w[e*4 + hd];
            float4 h_ = *reinterpret_cast<const float4*>(hb + (size_t)sh_src[e] * 256);
            acc.x += w_*h_.x; acc.y += w_*h_.y; acc.z += w_*h_.z; acc.w += w_*h_.w;
        }
        __syncthreads();
    }
    float inv = 1.f / sh_ws[hd];
    float4 b4 = *reinterpret_cast<const float4*>(&bias[t * 4]);
    float4 o;
    o.x = fmaxf(acc.x * inv + b4.x, 0.f);
    o.y = fmaxf(acc.y * inv + b4.y, 0.f);
    o.z = fmaxf(acc.z * inv + b4.z, 0.f);
    o.w = fmaxf(acc.w * inv + b4.w, 0.f);
    *reinterpret_cast<float4*>(&outp[(size_t)v * 256 + t * 4]) = o;
}

// ---------------- GAT aggregation H=1 (layer 3) ----------------
__global__ void gat_agg1_kernel(const float* __restrict__ bias) {
    float* __restrict__ outp = g_o3;
    const int v = blockIdx.x;
    const int t = threadIdx.x;      // 64
    const int lane = t & 31, warp = t >> 5;
    const int p0 = g_ptr[v];
    const int deg = g_ptr[v + 1] - p0;

    __shared__ float sh_ws[1];
    __shared__ float sh_m[1];
    __shared__ int   sh_src[CAP];
    __shared__ float sh_w[CAP];

    float dt0 = g_dt[v * 4];

    if (deg <= CAP) {
        for (int e = t; e < deg; e += 64) {
            int sN = g_csr[p0 + e];
            sh_src[e] = sN;
            sh_w[e] = leaky02(g_s[sN * 4] + dt0);
        }
        __syncthreads();
        if (warp == 0) {
            float mx = -1e30f;
            for (int e = lane; e < deg; e += 32) mx = fmaxf(mx, sh_w[e]);
#pragma unroll
            for (int o = 16; o > 0; o >>= 1) mx = fmaxf(mx, __shfl_xor_sync(0xffffffffu, mx, o));
            float sum = 0.f;
            for (int e = lane; e < deg; e += 32) {
                float w_ = __expf(sh_w[e] - mx);
                sh_w[e] = w_;
                sum += w_;
            }
#pragma unroll
            for (int o = 16; o > 0; o >>= 1) sum += __shfl_xor_sync(0xffffffffu, sum, o);
            if (lane == 0) sh_ws[0] = sum;
        }
        __syncthreads();

        float acc = 0.f;
        int e = 0;
        for (; e + 3 < deg; e += 4) {
            acc += sh_w[e+0] * g_h[(size_t)sh_src[e+0] * 64 + t];
            acc += sh_w[e+1] * g_h[(size_t)sh_src[e+1] * 64 + t];
            acc += sh_w[e+2] * g_h[(size_t)sh_src[e+2] * 64 + t];
            acc += sh_w[e+3] * g_h[(size_t)sh_src[e+3] * 64 + t];
        }
        for (; e < deg; e++) acc += sh_w[e] * g_h[(size_t)sh_src[e] * 64 + t];
        float o = acc / sh_ws[0] + bias[t];
        outp[(size_t)v * 64 + t] = fmaxf(o, 0.f);
        return;
    }

    if (warp == 0) {
        float mx = -1e30f;
        for (int e = lane; e < deg; e += 32) {
            int sN = g_csr[p0 + e];
            mx = fmaxf(mx, leaky02(g_s[sN * 4] + dt0));
        }
#pragma unroll
        for (int o = 16; o > 0; o >>= 1) mx = fmaxf(mx, __shfl_xor_sync(0xffffffffu, mx, o));
        float sum = 0.f;
        for (int e = lane; e < deg; e += 32) {
            int sN = g_csr[p0 + e];
            sum += __expf(leaky02(g_s[sN * 4] + dt0) - mx);
        }
#pragma unroll
        for (int o = 16; o > 0; o >>= 1) sum += __shfl_xor_sync(0xffffffffu, sum, o);
        if (lane == 0) { sh_m[0] = mx; sh_ws[0] = sum; }
    }
    __syncthreads();

    float acc = 0.f;
    for (int base = 0; base < deg; base += CAP) {
        int cnt = min(CAP, deg - base);
        for (int e = t; e < cnt; e += 64) {
            int sN = g_csr[p0 + base + e];
            sh_src[e] = sN;
            sh_w[e] = __expf(leaky02(g_s[sN * 4] + dt0) - sh_m[0]);
        }
        __syncthreads();
        for (int e = 0; e < cnt; e++)
            acc += sh_w[e] * g_h[(size_t)sh_src[e] * 64 + t];
        __syncthreads();
    }
    float o = acc / sh_ws[0] + bias[t];
    outp[(size_t)v * 64 + t] = fmaxf(o, 0.f);
}

// ---------------- fused pool + actor/critic heads ----------------
__global__ void heads_pool_kernel(const int* __restrict__ batch,
                                  const float* __restrict__ Wa1, const float* __restrict__ ba1,
                                  const float* __restrict__ Wa2, const float* __restrict__ ba2,
                                  const float* __restrict__ Wc1, const float* __restrict__ bc1,
                                  const float* __restrict__ Wc2, const float* __restrict__ bc2,
                                  float* __restrict__ out) {
    const int b = blockIdx.x;
    const int t = threadIdx.x;
    int lo = 0, hi = NN;
    while (lo < hi) { int mid = (lo + hi) >> 1; if (batch[mid] < b) lo = mid + 1; else hi = mid; }
    int start = lo;
    lo = start; hi = NN;
    while (lo < hi) { int mid = (lo + hi) >> 1; if (batch[mid] < b + 1) lo = mid + 1; else hi = mid; }
    int end = lo;
    int cnt = end - start;

    __shared__ float red[256];
    __shared__ float p[64], ha[64], hc[64];
    const int c = t & 63, stripe = t >> 6;
    float part = 0.f;
    for (int n = start + stripe; n < end; n += 4) part += g_o3[n * 64 + c];
    red[t] = part;
    __syncthreads();
    if (t < 64) {
        float s = red[t] + red[t + 64] + red[t + 128] + red[t + 192];
        float cc = cnt > 0 ? (float)cnt : 1.f;
        p[t] = s / cc;
    }
    __syncthreads();
    if (t < 64) {
        float aa = ba1[t], cv = bc1[t];
        for (int j = 0; j < 64; j++) { aa += p[j] * Wa1[j * 64 + t]; cv += p[j] * Wc1[j * 64 + t]; }
        ha[t] = fmaxf(aa, 0.f);
        hc[t] = fmaxf(cv, 0.f);
    }
    __syncthreads();
    for (int o = t; o < NEDGES_OUT; o += blockDim.x) {
        float acc = ba2[o];
        for (int j = 0; j < 64; j++) acc += ha[j] * Wa2[j * NEDGES_OUT + o];
        out[b * NEDGES_OUT + o] = tanhf(acc);
    }
    if (t == 0) {
        float acc = bc2[0];
        for (int j = 0; j < 64; j++) acc += hc[j] * Wc2[j];
        out[BGRAPH * NEDGES_OUT + b] = acc;
    }
}

// ---------------- launch ----------------
extern "C" void kernel_launch(void* const* d_in, const int* in_sizes, int n_in,
                              void* d_out, int out_size) {
    const float* x     = (const float*)d_in[0];
    const int*   ei    = (const int*)d_in[1];
    const int*   batch = (const int*)d_in[2];
    const float* W1  = (const float*)d_in[3];
    const float* as1 = (const float*)d_in[4];
    const float* ad1 = (const float*)d_in[5];
    const float* b1  = (const float*)d_in[6];
    const float* W2  = (const float*)d_in[7];
    const float* as2 = (const float*)d_in[8];
    const float* ad2 = (const float*)d_in[9];
    const float* b2  = (const float*)d_in[10];
    const float* W3  = (const float*)d_in[11];
    const float* as3 = (const float*)d_in[12];
    const float* ad3 = (const float*)d_in[13];
    const float* b3  = (const float*)d_in[14];
    const float* Wa1 = (const float*)d_in[15];
    const float* ba1 = (const float*)d_in[16];
    const float* Wa2 = (const float*)d_in[17];
    const float* ba2 = (const float*)d_in[18];
    const float* Wc1 = (const float*)d_in[19];
    const float* bc1 = (const float*)d_in[20];
    const float* Wc2 = (const float*)d_in[21];
    const float* bc2 = (const float*)d_in[22];
    float* out = (float*)d_out;

    static cudaStream_t s_csr = nullptr;
    static cudaEvent_t  ev_fork = nullptr, ev_join = nullptr;
    if (s_csr == nullptr) {
        cudaStreamCreateWithFlags(&s_csr, cudaStreamNonBlocking);
        cudaEventCreateWithFlags(&ev_fork, cudaEventDisableTiming);
        cudaEventCreateWithFlags(&ev_join, cudaEventDisableTiming);
    }

    const int MB = (NN + 63) / 64;   // 157

    // fork: CSR build concurrent with GEMM1
    cudaEventRecord(ev_fork, 0);
    cudaStreamWaitEvent(s_csr, ev_fork, 0);
    count_deg_kernel<<<(EALL + 255) / 256, 256, 0, s_csr>>>(ei);
    scan_kernel<<<1, 1024, 0, s_csr>>>();
    scatter_kernel<<<(EALL + 255) / 256, 256, 0, s_csr>>>(ei);
    cudaEventRecord(ev_join, s_csr);

    sgemm_fused_kernel<128, 4><<<dim3(2, MB), 128>>>(x, 0, W1, as1, ad1, NN, 128);

    cudaStreamWaitEvent(0, ev_join, 0);
    gat_agg4_kernel<<<NN, 64>>>(b1, 1);

    sgemm_fused_kernel<128, 4><<<dim3(2, MB), 128>>>(x, 1, W2, as2, ad2, NN, 256);
    gat_agg4_kernel<<<NN, 64>>>(b2, 2);

    sgemm_fused_kernel<64, 1><<<dim3(1, MB), 128>>>(x, 2, W3, as3, ad3, NN, 256);
    gat_agg1_kernel<<<NN, 64>>>(b3);

    heads_pool_kernel<<<BGRAPH, 256>>>(batch, Wa1, ba1, Wa2, ba2, Wc1, bc1, Wc2, bc2, out);
}

// round 15
// speedup vs baseline: 1.0835x; 1.0363x over previous
#include <cuda_runtime.h>
#include <math.h>
#include <stdint.h>

#define NN      10000
#define EE      320000
#define EALL    (EE + NN)
#define BGRAPH  64
#define NEDGES_OUT 1024
#define CAP     256

// ---------------- scratch ----------------
__device__ __align__(16) float g_h  [NN * 256];
__device__ __align__(16) float g_o1 [NN * 256];
__device__ __align__(16) float g_o2 [NN * 256];
__device__ __align__(16) float g_o3 [NN * 64];
__device__ __align__(16) float g_s  [NN * 4];
__device__ __align__(16) float g_dt [NN * 4];
__device__ int   g_deg [NN + 1];   // static zero-init; scan resets to 0 each run
__device__ int   g_ptr [NN + 1];
__device__ int   g_rank[EALL];
__device__ int   g_csr [EALL];

// ---------------- helpers ----------------
__device__ __forceinline__ void fma2(uint64_t& d, uint64_t a, uint64_t b) {
    asm("fma.rn.f32x2 %0,%1,%2,%0;" : "+l"(d) : "l"(a), "l"(b));
}
__device__ __forceinline__ uint64_t dup2(float v) {
    uint64_t r; asm("mov.b64 %0,{%1,%1};" : "=l"(r) : "f"(v)); return r;
}
__device__ __forceinline__ float2 upk2(uint64_t v) {
    float2 r; asm("mov.b64 {%0,%1},%2;" : "=f"(r.x), "=f"(r.y) : "l"(v)); return r;
}
__device__ __forceinline__ float leaky02(float z) { return z > 0.f ? z : 0.2f * z; }
__device__ __forceinline__ void cpa16(void* smem_ptr, const void* gptr) {
    uint32_t sa = (uint32_t)__cvta_generic_to_shared(smem_ptr);
    asm volatile("cp.async.cg.shared.global [%0], [%1], 16;" :: "r"(sa), "l"(gptr));
}

// ---------------- CSR build ----------------
__global__ void count_deg_kernel(const int* __restrict__ ei) {
    int e = blockIdx.x * blockDim.x + threadIdx.x;
    if (e >= EALL) return;
    int dst = (e < EE) ? ei[EE + e] : (e - EE);
    g_rank[e] = atomicAdd(&g_deg[dst], 1);
}

__global__ void scan_kernel() {
    __shared__ int sh[1024];
    const int t = threadIdx.x;
    const int PER = (NN + 1023) / 1024;
    int start = t * PER;
    int sum = 0;
    for (int i = 0; i < PER; i++) {
        int idx = start + i;
        if (idx < NN) sum += g_deg[idx];
    }
    sh[t] = sum;
    __syncthreads();
    for (int off = 1; off < 1024; off <<= 1) {
        int v = (t >= off) ? sh[t - off] : 0;
        __syncthreads();
        sh[t] += v;
        __syncthreads();
    }
    int run = (t == 0) ? 0 : sh[t - 1];
    for (int i = 0; i < PER; i++) {
        int idx = start + i;
        if (idx < NN) {
            int d = g_deg[idx];
            g_ptr[idx] = run;
            run += d;
            g_deg[idx] = 0;
        }
    }
    if (t == 1023) g_ptr[NN] = sh[1023];
}

__global__ void scatter_kernel(const int* __restrict__ ei) {
    int e = blockIdx.x * blockDim.x + threadIdx.x;
    if (e >= EALL) return;
    int src, dst;
    if (e < EE) { src = ei[e]; dst = ei[EE + e]; }
    else        { src = e - EE; dst = e - EE; }
    g_csr[g_ptr[dst] + g_rank[e]] = src;
}

// ---------------- SGEMM: 64 x TN tile, 128 threads, 8xTC f32x2 microtile ----------
// A: register-prefetched, transposed smem (LDS.128 row-pairs).
// B: cp.async double-buffered, issued one full tile ahead.
// __launch_bounds__(128, 2): grid only supplies ~2.1 blocks/SM, so cap at 2 and
// give ptxas 255 regs for deep LDS software pipelining across unrolled kk iters.
template <int TN, int H>
__global__ __launch_bounds__(128, 2)
void sgemm_fused_kernel(const float* __restrict__ Aext, int asel,
                        const float* __restrict__ W,
                        const float* __restrict__ as_, const float* __restrict__ ad_,
                        int M, int K) {
    constexpr int TC = TN / 16;
    constexpr int NCOL = H * 64;
    constexpr int NB4 = TN / 4;            // float4's per B k-row
    constexpr int BSTRIDE = 128 / NB4;     // k-rows per loader pass
    constexpr int BIT = 16 / BSTRIDE;      // cp.async per thread per tile
    __shared__ float sAT[2][16][64];
    __shared__ float sB [2][16][TN];

    const int t  = threadIdx.x;            // 128
    const int tx = t & 15, ty = t >> 4;    // ty 0..7
    const int brow = blockIdx.y * 64;
    const int bcol = blockIdx.x * TN;

    const int arow  = t & 63;
    const int kgA   = (t >> 6) * 8;        // 0 or 8
    const int arow_g = min(brow + arow, M - 1);   // clamped (garbage rows guarded at store)
    const int bc4 = (t % NB4) * 4;
    const int bkr = t / NB4;

    const float* __restrict__ A = (asel == 0) ? Aext
                                  : (asel == 1 ? (const float*)g_o1 : (const float*)g_o2);

    uint64_t acc[4][TC];
#pragma unroll
    for (int p = 0; p < 4; p++)
#pragma unroll
        for (int j = 0; j < TC; j++) acc[p][j] = 0ull;

    const int KT = K >> 4;
    float4 pa0, pa1;

    // prologue: A tile0 -> smem, B tile0+tile1 -> cp.async, A tile1 -> regs
    {
        const float* ap = A + (size_t)arow_g * K + kgA;
        pa0 = *reinterpret_cast<const float4*>(ap);
        pa1 = *reinterpret_cast<const float4*>(ap + 4);
        sAT[0][kgA + 0][arow] = pa0.x; sAT[0][kgA + 1][arow] = pa0.y;
        sAT[0][kgA + 2][arow] = pa0.z; sAT[0][kgA + 3][arow] = pa0.w;
        sAT[0][kgA + 4][arow] = pa1.x; sAT[0][kgA + 5][arow] = pa1.y;
        sAT[0][kgA + 6][arow] = pa1.z; sAT[0][kgA + 7][arow] = pa1.w;
#pragma unroll
        for (int i = 0; i < BIT; i++)
            cpa16(&sB[0][bkr + i * BSTRIDE][bc4],
                  W + (size_t)(bkr + i * BSTRIDE) * NCOL + bcol + bc4);
        asm volatile("cp.async.commit_group;");
#pragma unroll
        for (int i = 0; i < BIT; i++)
            cpa16(&sB[1][bkr + i * BSTRIDE][bc4],
                  W + (size_t)(16 + bkr + i * BSTRIDE) * NCOL + bcol + bc4);
        asm volatile("cp.async.commit_group;");
        if (KT > 1) {
            ap = A + (size_t)arow_g * K + 16 + kgA;
            pa0 = *reinterpret_cast<const float4*>(ap);
            pa1 = *reinterpret_cast<const float4*>(ap + 4);
        }
        asm volatile("cp.async.wait_group 1;" ::: "memory");
        __syncthreads();
    }

    for (int kt = 0; kt < KT; kt++) {
        const int p = kt & 1, q = p ^ 1;
#pragma unroll
        for (int kk = 0; kk < 16; kk++) {
            ulonglong2 a01 = *reinterpret_cast<const ulonglong2*>(&sAT[p][kk][ty * 8]);
            ulonglong2 a23 = *reinterpret_cast<const ulonglong2*>(&sAT[p][kk][ty * 8 + 4]);
            float4 B0 = *reinterpret_cast<const float4*>(&sB[p][kk][tx * TC]);
            uint64_t bd[TC];
            bd[0] = dup2(B0.x); bd[1] = dup2(B0.y); bd[2] = dup2(B0.z); bd[3] = dup2(B0.w);
            if (TC == 8) {
                float4 B1 = *reinterpret_cast<const float4*>(&sB[p][kk][tx * TC + 4]);
                bd[4] = dup2(B1.x); bd[5] = dup2(B1.y); bd[6] = dup2(B1.z); bd[7] = dup2(B1.w);
            }
#pragma unroll
            for (int j = 0; j < TC; j++) {
                fma2(acc[0][j], a01.x, bd[j]);
                fma2(acc[1][j], a01.y, bd[j]);
                fma2(acc[2][j], a23.x, bd[j]);
                fma2(acc[3][j], a23.y, bd[j]);
            }
        }
        __syncthreads();     // all warps done reading buffer p (A and B)
        if (kt + 1 < KT) {
            // A(kt+1) regs -> sAT[q]
            sAT[q][kgA + 0][arow] = pa0.x; sAT[q][kgA + 1][arow] = pa0.y;
            sAT[q][kgA + 2][arow] = pa0.z; sAT[q][kgA + 3][arow] = pa0.w;
            sAT[q][kgA + 4][arow] = pa1.x; sAT[q][kgA + 5][arow] = pa1.y;
            sAT[q][kgA + 6][arow] = pa1.z; sAT[q][kgA + 7][arow] = pa1.w;
            if (kt + 2 < KT) {
                const int k0 = (kt + 2) * 16;
                const float* ap = A + (size_t)arow_g * K + k0 + kgA;
                pa0 = *reinterpret_cast<const float4*>(ap);
                pa1 = *reinterpret_cast<const float4*>(ap + 4);
#pragma unroll
                for (int i = 0; i < BIT; i++)
                    cpa16(&sB[p][bkr + i * BSTRIDE][bc4],
                          W + (size_t)(k0 + bkr + i * BSTRIDE) * NCOL + bcol + bc4);
                asm volatile("cp.async.commit_group;");
                asm volatile("cp.async.wait_group 1;" ::: "memory");
            } else {
                asm volatile("cp.async.wait_group 0;" ::: "memory");
            }
            __syncthreads();
        }
    }

    // unpack
    float c[8][TC];
#pragma unroll
    for (int rp = 0; rp < 4; rp++)
#pragma unroll
        for (int j = 0; j < TC; j++) {
            float2 u = upk2(acc[rp][j]);
            c[2*rp][j] = u.x; c[2*rp+1][j] = u.y;
        }

    const int col0 = bcol + tx * TC;
    const int head = col0 >> 6;
    float avv[TC], dvv[TC];
#pragma unroll
    for (int j = 0; j < TC; j++) {
        avv[j] = as_[head * 64 + ((col0 + j) & 63)];
        dvv[j] = ad_[head * 64 + ((col0 + j) & 63)];
    }
    constexpr int G = 64 / TC;

#pragma unroll
    for (int r = 0; r < 8; r++) {
        int rg = brow + ty * 8 + r;
        bool ok = rg < M;
        if (ok) {
            float* cp = g_h + (size_t)rg * NCOL + col0;
#pragma unroll
            for (int j = 0; j < TC; j += 4)
                *reinterpret_cast<float4*>(cp + j) =
                    make_float4(c[r][j], c[r][j+1], c[r][j+2], c[r][j+3]);
        }
        float sv = 0.f, dv = 0.f;
#pragma unroll
        for (int j = 0; j < TC; j++) { sv += c[r][j] * avv[j]; dv += c[r][j] * dvv[j]; }
#pragma unroll
        for (int o = G / 2; o > 0; o >>= 1) {
            sv += __shfl_xor_sync(0xffffffffu, sv, o);
            dv += __shfl_xor_sync(0xffffffffu, dv, o);
        }
        if (ok && (tx % G) == 0) {
            g_s [rg * 4 + head] = sv;
            g_dt[rg * 4 + head] = dv;
        }
    }
}

// ---------------- GAT aggregation H=4: 64 threads, float4/thread ----------------
__global__ void gat_agg4_kernel(const float* __restrict__ bias, int osel) {
    float* __restrict__ outp = (osel == 1) ? g_o1 : g_o2;
    const int v = blockIdx.x;
    const int t = threadIdx.x;          // 64
    const int lane = t & 31, warp = t >> 5;
    const int hd = t >> 4;
    const int p0 = g_ptr[v];
    const int deg = g_ptr[v + 1] - p0;

    __shared__ float sh_ws[4];
    __shared__ float sh_m[4];
    __shared__ int   sh_src[CAP];
    __shared__ float sh_w[CAP * 4];

    float dt[4];
    {
        float4 d4 = *reinterpret_cast<const float4*>(&g_dt[v * 4]);
        dt[0] = d4.x; dt[1] = d4.y; dt[2] = d4.z; dt[3] = d4.w;
    }

    if (deg <= CAP) {
        for (int e = t; e < deg; e += 64) {
            int sN = g_csr[p0 + e];
            sh_src[e] = sN;
            float4 s4 = *reinterpret_cast<const float4*>(&g_s[sN * 4]);
            sh_w[e * 4 + 0] = leaky02(s4.x + dt[0]);
            sh_w[e * 4 + 1] = leaky02(s4.y + dt[1]);
            sh_w[e * 4 + 2] = leaky02(s4.z + dt[2]);
            sh_w[e * 4 + 3] = leaky02(s4.w + dt[3]);
        }
        __syncthreads();
#pragma unroll
        for (int k = 0; k < 2; k++) {
            int hh = warp * 2 + k;
            float mx = -1e30f;
            for (int e = lane; e < deg; e += 32) mx = fmaxf(mx, sh_w[e * 4 + hh]);
#pragma unroll
            for (int o = 16; o > 0; o >>= 1) mx = fmaxf(mx, __shfl_xor_sync(0xffffffffu, mx, o));
            float sum = 0.f;
            for (int e = lane; e < deg; e += 32) {
                float w_ = __expf(sh_w[e * 4 + hh] - mx);
                sh_w[e * 4 + hh] = w_;
                sum += w_;
            }
#pragma unroll
            for (int o = 16; o > 0; o >>= 1) sum += __shfl_xor_sync(0xffffffffu, sum, o);
            if (lane == 0) sh_ws[hh] = sum;
        }
        __syncthreads();

        float4 acc = make_float4(0.f, 0.f, 0.f, 0.f);
        const float* __restrict__ hb = g_h + t * 4;
        int e = 0;
        for (; e + 3 < deg; e += 4) {
            float w0 = sh_w[(e+0)*4 + hd], w1 = sh_w[(e+1)*4 + hd];
            float w2 = sh_w[(e+2)*4 + hd], w3 = sh_w[(e+3)*4 + hd];
            float4 h0 = *reinterpret_cast<const float4*>(hb + (size_t)sh_src[e+0] * 256);
            float4 h1 = *reinterpret_cast<const float4*>(hb + (size_t)sh_src[e+1] * 256);
            float4 h2 = *reinterpret_cast<const float4*>(hb + (size_t)sh_src[e+2] * 256);
            float4 h3 = *reinterpret_cast<const float4*>(hb + (size_t)sh_src[e+3] * 256);
            acc.x += w0*h0.x + w1*h1.x + w2*h2.x + w3*h3.x;
            acc.y += w0*h0.y + w1*h1.y + w2*h2.y + w3*h3.y;
            acc.z += w0*h0.z + w1*h1.z + w2*h2.z + w3*h3.z;
            acc.w += w0*h0.w + w1*h1.w + w2*h2.w + w3*h3.w;
        }
        for (; e < deg; e++) {
            float w_ = sh_w[e*4 + hd];
            float4 h_ = *reinterpret_cast<const float4*>(hb + (size_t)sh_src[e] * 256);
            acc.x += w_*h_.x; acc.y += w_*h_.y; acc.z += w_*h_.z; acc.w += w_*h_.w;
        }
        float inv = 1.f / sh_ws[hd];
        float4 b4 = *reinterpret_cast<const float4*>(&bias[t * 4]);
        float4 o;
        o.x = fmaxf(acc.x * inv + b4.x, 0.f);
        o.y = fmaxf(acc.y * inv + b4.y, 0.f);
        o.z = fmaxf(acc.z * inv + b4.z, 0.f);
        o.w = fmaxf(acc.w * inv + b4.w, 0.f);
        *reinterpret_cast<float4*>(&outp[(size_t)v * 256 + t * 4]) = o;
        return;
    }

    // ---- fallback deg > CAP ----
#pragma unroll
    for (int k = 0; k < 2; k++) {
        int hh = warp * 2 + k;
        float mx = -1e30f;
        for (int e = lane; e < deg; e += 32) {
            int sN = g_csr[p0 + e];
            mx = fmaxf(mx, leaky02(g_s[sN * 4 + hh] + dt[hh]));
        }
#pragma unroll
        for (int o = 16; o > 0; o >>= 1) mx = fmaxf(mx, __shfl_xor_sync(0xffffffffu, mx, o));
        float sum = 0.f;
        for (int e = lane; e < deg; e += 32) {
            int sN = g_csr[p0 + e];
            sum += __expf(leaky02(g_s[sN * 4 + hh] + dt[hh]) - mx);
        }
#pragma unroll
        for (int o = 16; o > 0; o >>= 1) sum += __shfl_xor_sync(0xffffffffu, sum, o);
        if (lane == 0) { sh_m[hh] = mx; sh_ws[hh] = sum; }
    }
    __syncthreads();

    float4 acc = make_float4(0.f, 0.f, 0.f, 0.f);
    const float* __restrict__ hb = g_h + t * 4;
    for (int base = 0; base < deg; base += CAP) {
        int cnt = min(CAP, deg - base);
        for (int e = t; e < cnt; e += 64) {
            int sN = g_csr[p0 + base + e];
            sh_src[e] = sN;
            float4 s4 = *reinterpret_cast<const float4*>(&g_s[sN * 4]);
            sh_w[e*4+0] = __expf(leaky02(s4.x + dt[0]) - sh_m[0]);
            sh_w[e*4+1] = __expf(leaky02(s4.y + dt[1]) - sh_m[1]);
            sh_w[e*4+2] = __expf(leaky02(s4.z + dt[2]) - sh_m[2]);
            sh_w[e*4+3] = __expf(leaky02(s4.w + dt[3]) - sh_m[3]);
        }
        __syncthreads();
        for (int e = 0; e < cnt; e++) {
            float w_ = sh_w[e*4 + hd];
            float4 h_ = *reinterpret_cast<const float4*>(hb + (size_t)sh_src[e] * 256);
            acc.x += w_*h_.x; acc.y += w_*h_.y; acc.z += w_*h_.z; acc.w += w_*h_.w;
        }
        __syncthreads();
    }
    float inv = 1.f / sh_ws[hd];
    float4 b4 = *reinterpret_cast<const float4*>(&bias[t * 4]);
    float4 o;
    o.x = fmaxf(acc.x * inv + b4.x, 0.f);
    o.y = fmaxf(acc.y * inv + b4.y, 0.f);
    o.z = fmaxf(acc.z * inv + b4.z, 0.f);
    o.w = fmaxf(acc.w * inv + b4.w, 0.f);
    *reinterpret_cast<float4*>(&outp[(size_t)v * 256 + t * 4]) = o;
}

// ---------------- GAT aggregation H=1 (layer 3) ----------------
__global__ void gat_agg1_kernel(const float* __restrict__ bias) {
    float* __restrict__ outp = g_o3;
    const int v = blockIdx.x;
    const int t = threadIdx.x;      // 64
    const int lane = t & 31, warp = t >> 5;
    const int p0 = g_ptr[v];
    const int deg = g_ptr[v + 1] - p0;

    __shared__ float sh_ws[1];
    __shared__ float sh_m[1];
    __shared__ int   sh_src[CAP];
    __shared__ float sh_w[CAP];

    float dt0 = g_dt[v * 4];

    if (deg <= CAP) {
        for (int e = t; e < deg; e += 64) {
            int sN = g_csr[p0 + e];
            sh_src[e] = sN;
            sh_w[e] = leaky02(g_s[sN * 4] + dt0);
        }
        __syncthreads();
        if (warp == 0) {
            float mx = -1e30f;
            for (int e = lane; e < deg; e += 32) mx = fmaxf(mx, sh_w[e]);
#pragma unroll
            for (int o = 16; o > 0; o >>= 1) mx = fmaxf(mx, __shfl_xor_sync(0xffffffffu, mx, o));
            float sum = 0.f;
            for (int e = lane; e < deg; e += 32) {
                float w_ = __expf(sh_w[e] - mx);
                sh_w[e] = w_;
                sum += w_;
            }
#pragma unroll
            for (int o = 16; o > 0; o >>= 1) sum += __shfl_xor_sync(0xffffffffu, sum, o);
            if (lane == 0) sh_ws[0] = sum;
        }
        __syncthreads();

        float acc = 0.f;
        int e = 0;
        for (; e + 3 < deg; e += 4) {
            acc += sh_w[e+0] * g_h[(size_t)sh_src[e+0] * 64 + t];
            acc += sh_w[e+1] * g_h[(size_t)sh_src[e+1] * 64 + t];
            acc += sh_w[e+2] * g_h[(size_t)sh_src[e+2] * 64 + t];
            acc += sh_w[e+3] * g_h[(size_t)sh_src[e+3] * 64 + t];
        }
        for (; e < deg; e++) acc += sh_w[e] * g_h[(size_t)sh_src[e] * 64 + t];
        float o = acc / sh_ws[0] + bias[t];
        outp[(size_t)v * 64 + t] = fmaxf(o, 0.f);
        return;
    }

    if (warp == 0) {
        float mx = -1e30f;
        for (int e = lane; e < deg; e += 32) {
            int sN = g_csr[p0 + e];
            mx = fmaxf(mx, leaky02(g_s[sN * 4] + dt0));
        }
#pragma unroll
        for (int o = 16; o > 0; o >>= 1) mx = fmaxf(mx, __shfl_xor_sync(0xffffffffu, mx, o));
        float sum = 0.f;
        for (int e = lane; e < deg; e += 32) {
            int sN = g_csr[p0 + e];
            sum += __expf(leaky02(g_s[sN * 4] + dt0) - mx);
        }
#pragma unroll
        for (int o = 16; o > 0; o >>= 1) sum += __shfl_xor_sync(0xffffffffu, sum, o);
        if (lane == 0) { sh_m[0] = mx; sh_ws[0] = sum; }
    }
    __syncthreads();

    float acc = 0.f;
    for (int base = 0; base < deg; base += CAP) {
        int cnt = min(CAP, deg - base);
        for (int e = t; e < cnt; e += 64) {
            int sN = g_csr[p0 + base + e];
            sh_src[e] = sN;
            sh_w[e] = __expf(leaky02(g_s[sN * 4] + dt0) - sh_m[0]);
        }
        __syncthreads();
        for (int e = 0; e < cnt; e++)
            acc += sh_w[e] * g_h[(size_t)sh_src[e] * 64 + t];
        __syncthreads();
    }
    float o = acc / sh_ws[0] + bias[t];
    outp[(size_t)v * 64 + t] = fmaxf(o, 0.f);
}

// ---------------- fused pool + actor/critic heads ----------------
__global__ void heads_pool_kernel(const int* __restrict__ batch,
                                  const float* __restrict__ Wa1, const float* __restrict__ ba1,
                                  const float* __restrict__ Wa2, const float* __restrict__ ba2,
                                  const float* __restrict__ Wc1, const float* __restrict__ bc1,
                                  const float* __restrict__ Wc2, const float* __restrict__ bc2,
                                  float* __restrict__ out) {
    const int b = blockIdx.x;
    const int t = threadIdx.x;
    int lo = 0, hi = NN;
    while (lo < hi) { int mid = (lo + hi) >> 1; if (batch[mid] < b) lo = mid + 1; else hi = mid; }
    int start = lo;
    lo = start; hi = NN;
    while (lo < hi) { int mid = (lo + hi) >> 1; if (batch[mid] < b + 1) lo = mid + 1; else hi = mid; }
    int end = lo;
    int cnt = end - start;

    __shared__ float red[256];
    __shared__ float p[64], ha[64], hc[64];
    const int c = t & 63, stripe = t >> 6;
    float part = 0.f;
    for (int n = start + stripe; n < end; n += 4) part += g_o3[n * 64 + c];
    red[t] = part;
    __syncthreads();
    if (t < 64) {
        float s = red[t] + red[t + 64] + red[t + 128] + red[t + 192];
        float cc = cnt > 0 ? (float)cnt : 1.f;
        p[t] = s / cc;
    }
    __syncthreads();
    if (t < 64) {
        float aa = ba1[t], cv = bc1[t];
        for (int j = 0; j < 64; j++) { aa += p[j] * Wa1[j * 64 + t]; cv += p[j] * Wc1[j * 64 + t]; }
        ha[t] = fmaxf(aa, 0.f);
        hc[t] = fmaxf(cv, 0.f);
    }
    __syncthreads();
    for (int o = t; o < NEDGES_OUT; o += blockDim.x) {
        float acc = ba2[o];
        for (int j = 0; j < 64; j++) acc += ha[j] * Wa2[j * NEDGES_OUT + o];
        out[b * NEDGES_OUT + o] = tanhf(acc);
    }
    if (t == 0) {
        float acc = bc2[0];
        for (int j = 0; j < 64; j++) acc += hc[j] * Wc2[j];
        out[BGRAPH * NEDGES_OUT + b] = acc;
    }
}

// ---------------- launch ----------------
extern "C" void kernel_launch(void* const* d_in, const int* in_sizes, int n_in,
                              void* d_out, int out_size) {
    const float* x     = (const float*)d_in[0];
    const int*   ei    = (const int*)d_in[1];
    const int*   batch = (const int*)d_in[2];
    const float* W1  = (const float*)d_in[3];
    const float* as1 = (const float*)d_in[4];
    const float* ad1 = (const float*)d_in[5];
    const float* b1  = (const float*)d_in[6];
    const float* W2  = (const float*)d_in[7];
    const float* as2 = (const float*)d_in[8];
    const float* ad2 = (const float*)d_in[9];
    const float* b2  = (const float*)d_in[10];
    const float* W3  = (const float*)d_in[11];
    const float* as3 = (const float*)d_in[12];
    const float* ad3 = (const float*)d_in[13];
    const float* b3  = (const float*)d_in[14];
    const float* Wa1 = (const float*)d_in[15];
    const float* ba1 = (const float*)d_in[16];
    const float* Wa2 = (const float*)d_in[17];
    const float* ba2 = (const float*)d_in[18];
    const float* Wc1 = (const float*)d_in[19];
    const float* bc1 = (const float*)d_in[20];
    const float* Wc2 = (const float*)d_in[21];
    const float* bc2 = (const float*)d_in[22];
    float* out = (float*)d_out;

    static cudaStream_t s_csr = nullptr;
    static cudaEvent_t  ev_fork = nullptr, ev_join = nullptr;
    if (s_csr == nullptr) {
        cudaStreamCreateWithFlags(&s_csr, cudaStreamNonBlocking);
        cudaEventCreateWithFlags(&ev_fork, cudaEventDisableTiming);
        cudaEventCreateWithFlags(&ev_join, cudaEventDisableTiming);
    }

    const int MB = (NN + 63) / 64;   // 157

    // fork: CSR build concurrent with GEMM1
    cudaEventRecord(ev_fork, 0);
    cudaStreamWaitEvent(s_csr, ev_fork, 0);
    count_deg_kernel<<<(EALL + 255) / 256, 256, 0, s_csr>>>(ei);
    scan_kernel<<<1, 1024, 0, s_csr>>>();
    scatter_kernel<<<(EALL + 255) / 256, 256, 0, s_csr>>>(ei);
    cudaEventRecord(ev_join, s_csr);

    sgemm_fused_kernel<128, 4><<<dim3(2, MB), 128>>>(x, 0, W1, as1, ad1, NN, 128);

    cudaStreamWaitEvent(0, ev_join, 0);
    gat_agg4_kernel<<<NN, 64>>>(b1, 1);

    sgemm_fused_kernel<128, 4><<<dim3(2, MB), 128>>>(x, 1, W2, as2, ad2, NN, 256);
    gat_agg4_kernel<<<NN, 64>>>(b2, 2);

    sgemm_fused_kernel<64, 1><<<dim3(1, MB), 128>>>(x, 2, W3, as3, ad3, NN, 256);
    gat_agg1_kernel<<<NN, 64>>>(b3);

    heads_pool_kernel<<<BGRAPH, 256>>>(batch, Wa1, ba1, Wa2, ba2, Wc1, bc1, Wc2, bc2, out);
}